// round 5
// baseline (speedup 1.0000x reference)
#include <cuda_runtime.h>
#include <cstdint>

#define BS 4
#define SEQ 1024
#define DIN 1024
#define DOUT 1024
#define NKR 32

// ---------------- scratch ----------------
__device__ __align__(128) float g_Xc[BS * SEQ * DIN];   // tf32-rounded X (written by router)
__device__ __align__(128) float g_Wc[DOUT * DIN];       // tf32-rounded W
__device__ __align__(128) float g_Y[BS * NKR * SEQ];    // y = x@A -> cumsum over s  [b][kr][s]
__device__ __align__(128) float g_mw[BS * SEQ * 8];     // router logits
__device__ __align__(128) float g_WR[BS * SEQ * NKR];   // adapter K-extension (A side), tf32-rounded
__device__ __align__(128) float g_BE[DOUT * NKR];       // B_flat transposed [n][kr], tf32-rounded
__device__ __align__(128) float g_PHIA[40 * DIN];       // [phi|A] transposed, k-contiguous
__device__ int g_meta[8];

// ---------------- helpers ----------------
__device__ __forceinline__ uint32_t smem_u32(const void* p) {
    uint32_t a;
    asm("{ .reg .u64 t; cvta.to.shared.u64 t, %1; cvt.u32.u64 %0, t; }" : "=r"(a) : "l"(p));
    return a;
}
#define CP16(dst, src)  asm volatile("cp.async.cg.shared.global [%0], [%1], 16;" :: "r"(dst), "l"(src))
#define CP_COMMIT()     asm volatile("cp.async.commit_group;" ::: "memory")
#define CP_WAIT(n)      asm volatile("cp.async.wait_group %0;" :: "n"(n) : "memory")

__device__ __forceinline__ uint32_t f2tf32(float f) {
    uint32_t u;
    asm("cvt.rna.tf32.f32 %0, %1;" : "=r"(u) : "f"(f));
    return u;
}
__device__ __forceinline__ void mma_tf32(float c[4], const uint32_t a[4], const uint32_t b[2]) {
    asm volatile(
        "mma.sync.aligned.m16n8k8.row.col.f32.tf32.tf32.f32 "
        "{%0,%1,%2,%3}, {%4,%5,%6,%7}, {%8,%9}, {%0,%1,%2,%3};"
        : "+f"(c[0]), "+f"(c[1]), "+f"(c[2]), "+f"(c[3])
        : "r"(a[0]), "r"(a[1]), "r"(a[2]), "r"(a[3]), "r"(b[0]), "r"(b[1]));
}

// ---------------- K0: setup — mask params, PHIA/BE transposes, W->tf32 ----------------
__global__ void __launch_bounds__(256) setup_kernel(const float* __restrict__ phi,
                                                    const float* __restrict__ la,
                                                    const float* __restrict__ lb,
                                                    const float* __restrict__ W,
                                                    const int* __restrict__ inst,
                                                    const int* __restrict__ pad) {
    int bx = blockIdx.x, tid = threadIdx.x;
    if (bx < 4) {
        int b = bx;
        const int* ib = inst + b * SEQ;
        const int* pb = pad + b * SEQ;
        __shared__ int s_sum, s_fi, s_fp;
        if (tid == 0) { s_sum = 0; s_fi = 1 << 30; s_fp = 1 << 30; }
        __syncthreads();
        int lsum = 0, lfi = 1 << 30, lfp = 1 << 30;
        for (int i = tid; i < SEQ; i += 256) {
            int iv = ib[i];
            lsum += iv;
            if (iv && i < lfi) lfi = i;
            if (pb[i] && i < lfp) lfp = i;
        }
        atomicAdd(&s_sum, lsum);
        atomicMin(&s_fi, lfi);
        atomicMin(&s_fp, lfp);
        __syncthreads();
        if (tid == 0) {
            int fi = (s_fi == (1 << 30)) ? 0 : s_fi;
            int fp = (s_fp == (1 << 30)) ? 0 : s_fp;
            g_meta[b] = fi + s_sum;
            g_meta[4 + b] = fp;
        }
    } else if (bx < 8) {
        for (int idx = (bx - 4) * 256 + tid; idx < 40 * DIN + DOUT * NKR; idx += 1024) {
            if (idx < 40 * DIN) {
                int n = idx >> 10, k = idx & 1023;
                float v;
                if (n < 8) v = phi[k * 8 + n];
                else { int kr = n - 8; v = la[(kr >> 2) * (DIN * 4) + k * 4 + (kr & 3)]; }
                g_PHIA[idx] = v;
            } else {
                int i2 = idx - 40 * DIN;
                int n = i2 >> 5, kr = i2 & 31;
                g_BE[i2] = __uint_as_float(f2tf32(lb[kr * DOUT + n]));
            }
        }
    } else {
        int id = (bx - 8) * 256 + tid;   // 0..32767
#pragma unroll
        for (int j = 0; j < 8; j++) {
            int f4 = j * 32768 + id;
            float4 v = ((const float4*)W)[f4];
            uint4 u;
            u.x = f2tf32(v.x); u.y = f2tf32(v.y); u.z = f2tf32(v.z); u.w = f2tf32(v.w);
            ((uint4*)g_Wc)[f4] = u;
        }
    }
}

// ---------------- K2: router GEMM  [mw|y] = X @ [phi|A]; writes g_Xc as byproduct ----------------
// BM=64, N=40, BK=32, 128 threads, 6-stage cp.async pipeline (clean drained tail).
#define R_NS 6
#define R_AF (64 * 36)
#define R_BF (40 * 36)
#define R_STAGE (R_AF + R_BF)
#define R_SMEM (R_NS * R_STAGE * 4)

__global__ void __launch_bounds__(128) router_mma(const float* __restrict__ X) {
    extern __shared__ float sm[];
    int tid = threadIdx.x, wid = tid >> 5, lane = tid & 31;
    int m0 = blockIdx.x * 64;
    float acc[5][4];
#pragma unroll
    for (int n = 0; n < 5; n++)
#pragma unroll
        for (int j = 0; j < 4; j++) acc[n][j] = 0.f;

#define R_ISSUE(it) do {                                                              \
        int _slot = (it) % R_NS;                                                      \
        float* _A = sm + _slot * R_STAGE;                                             \
        float* _B = _A + R_AF;                                                        \
        int _k0 = (it) * 32;                                                          \
        for (int c = tid; c < 832; c += 128) {                                        \
            if (c < 512) {                                                            \
                int r = c >> 3, cc = c & 7;                                           \
                CP16(smem_u32(&_A[r * 36 + cc * 4]),                                  \
                     X + (size_t)(m0 + r) * DIN + _k0 + cc * 4);                      \
            } else {                                                                  \
                int c2 = c - 512, r = c2 >> 3, cc = c2 & 7;                           \
                CP16(smem_u32(&_B[r * 36 + cc * 4]),                                  \
                     g_PHIA + (size_t)r * DIN + _k0 + cc * 4);                        \
            }                                                                         \
        }                                                                             \
        CP_COMMIT();                                                                  \
    } while (0)

#define R_COMPUTE(i) do {                                                             \
        int _slot2 = (i) % R_NS;                                                      \
        float* A = sm + _slot2 * R_STAGE;                                             \
        float* B = A + R_AF;                                                          \
        int k0 = (i) * 32;                                                            \
        _Pragma("unroll")                                                             \
        for (int ka = 0; ka < 4; ka++) {                                              \
            int kk = ka * 8 + (lane & 3);                                             \
            int row = wid * 16 + (lane >> 2);                                         \
            uint32_t a[4];                                                            \
            a[0] = f2tf32(A[row * 36 + kk]);                                          \
            a[1] = f2tf32(A[(row + 8) * 36 + kk]);                                    \
            a[2] = f2tf32(A[row * 36 + kk + 4]);                                      \
            a[3] = f2tf32(A[(row + 8) * 36 + kk + 4]);                                \
            _Pragma("unroll")                                                         \
            for (int n = 0; n < 5; n++) {                                             \
                int nr = n * 8 + (lane >> 2);                                         \
                uint32_t b[2];                                                        \
                b[0] = f2tf32(B[nr * 36 + kk]);                                       \
                b[1] = f2tf32(B[nr * 36 + kk + 4]);                                   \
                mma_tf32(acc[n], a, b);                                               \
            }                                                                         \
        }                                                                             \
        _Pragma("unroll")                                                             \
        for (int j = 0; j < 4; j++) {                                                 \
            int c = tid + j * 128;                                                    \
            int r = c >> 3, cc = c & 7;                                               \
            float4 v = *(const float4*)&A[r * 36 + cc * 4];                           \
            uint4 u;                                                                  \
            u.x = f2tf32(v.x); u.y = f2tf32(v.y);                                     \
            u.z = f2tf32(v.z); u.w = f2tf32(v.w);                                     \
            *(uint4*)&g_Xc[(size_t)(m0 + r) * DIN + k0 + cc * 4] = u;                 \
        }                                                                             \
    } while (0)

#pragma unroll
    for (int it = 0; it < 5; it++) R_ISSUE(it);

    // main loop: real prefetch remains (i+5 <= 31)
    for (int i = 0; i < 27; i++) {
        CP_WAIT(4);
        __syncthreads();
        R_COMPUTE(i);
        R_ISSUE(i + 5);
    }
    // drained tail: all remaining stages resident
    CP_WAIT(0);
    __syncthreads();
    for (int i = 27; i < 32; i++) R_COMPUTE(i);

    // scatter D
    int row = m0 + wid * 16 + (lane >> 2);
#pragma unroll
    for (int n = 0; n < 5; n++) {
#pragma unroll
        for (int j = 0; j < 4; j++) {
            int m = row + ((j >> 1) << 3);
            int col = n * 8 + (lane & 3) * 2 + (j & 1);
            int b = m >> 10, s = m & 1023;
            if (col < 8) g_mw[(((size_t)b << 10) + s) * 8 + col] = acc[n][j];
            else g_Y[((size_t)b * NKR + (col - 8)) * SEQ + s] = acc[n][j];
        }
    }
}

// ---------------- K3: inclusive cumsum (float4 + warp scan) ----------------
__global__ void __launch_bounds__(256) scan_kernel() {
    int tid = threadIdx.x, wid = tid >> 5, lane = tid & 31;
    size_t base = (size_t)blockIdx.x * SEQ;
    float4 v = ((float4*)(g_Y + base))[tid];
    v.y += v.x; v.z += v.y; v.w += v.z;
    float t = v.w;
#pragma unroll
    for (int off = 1; off < 32; off <<= 1) {
        float u = __shfl_up_sync(0xffffffffu, t, off);
        if (lane >= off) t += u;
    }
    float warp_excl = t - v.w;
    __shared__ float wsum[8];
    if (lane == 31) wsum[wid] = t;
    __syncthreads();
    if (wid == 0) {
        float w = (lane < 8) ? wsum[lane] : 0.f;
#pragma unroll
        for (int off = 1; off < 8; off <<= 1) {
            float u = __shfl_up_sync(0xffffffffu, w, off);
            if (lane >= off) w += u;
        }
        if (lane < 8) wsum[lane] = w;
    }
    __syncthreads();
    float blk = warp_excl + (wid > 0 ? wsum[wid - 1] : 0.f);
    v.x += blk; v.y += blk; v.z += blk; v.w += blk;
    ((float4*)(g_Y + base))[tid] = v;
}

// ---------------- K4: wr weights (tf32-rounded) ----------------
__global__ void __launch_bounds__(128) wr_prep(const int* __restrict__ pad) {
    int token = blockIdx.x * 128 + threadIdx.x;
    int b = token >> 10, s = token & 1023;
    float* wr = g_WR + (size_t)token * NKR;
    if (pad[(b << 10) + s] == 0) {
#pragma unroll
        for (int kr = 0; kr < NKR; kr++) wr[kr] = 0.f;
        return;
    }
    int thresh = g_meta[b], pstart = g_meta[4 + b];
    float mwv[8];
    float mx = -1e30f;
#pragma unroll
    for (int j = 0; j < 8; j++) {
        mwv[j] = g_mw[((((size_t)b << 10) + s) << 3) + j];
        mx = fmaxf(mx, mwv[j]);
    }
    float se = 0.f;
#pragma unroll
    for (int j = 0; j < 8; j++) { mwv[j] = expf(mwv[j] - mx); se += mwv[j]; }
    float inv_se = 1.f / se;
    int m = max(thresh, s + 1);
    int cnt = m - pstart;
    if (cnt < 1) cnt = 1;
    float invc = 1.f / (float)cnt;
#pragma unroll
    for (int kr = 0; kr < NKR; kr++) {
        const float* yp = g_Y + ((size_t)b * NKR + kr) * SEQ;
        float wsum = yp[m - 1] - (pstart > 0 ? yp[pstart - 1] : 0.f);
        wr[kr] = __uint_as_float(f2tf32(mwv[kr >> 2] * inv_se * wsum * invc));
    }
}

// ---------------- K5: fused GEMM  out = [Xc|wr] @ [[Wc^T];[BE]] + bias ----------------
// BM=128, BN=256, BK=32, K=1056 (33 tiles). 8 warps of 64x64. 3-stage cp.async, drained tail.
#define G_NS 3
#define G_AF (128 * 36)
#define G_BF (256 * 36)
#define G_STAGE (G_AF + G_BF)
#define G_SMEM (G_NS * G_STAGE * 4)

__global__ void __launch_bounds__(256) gemm_mma(const float* __restrict__ bias,
                                                float* __restrict__ out) {
    extern __shared__ float sm[];
    int tid = threadIdx.x, wid = tid >> 5, lane = tid & 31;
    int wm = wid >> 2, wn = wid & 3;
    int m0 = blockIdx.y * 128, n0 = blockIdx.x * 256;

    float acc[4][8][4];
#pragma unroll
    for (int i = 0; i < 4; i++)
#pragma unroll
        for (int j = 0; j < 8; j++)
#pragma unroll
            for (int k = 0; k < 4; k++) acc[i][j][k] = 0.f;

#define G_ISSUE(it) do {                                                              \
        int _slot = (it) % G_NS;                                                      \
        float* _A = sm + _slot * G_STAGE;                                             \
        float* _B = _A + G_AF;                                                        \
        int _k0 = (it) * 32;                                                          \
        bool _ext = ((it) == 32);                                                     \
        for (int c = tid; c < 3072; c += 256) {                                       \
            if (c < 1024) {                                                           \
                int r = c >> 3, cc = c & 7;                                           \
                const float* _s = _ext ? g_WR + (size_t)(m0 + r) * NKR + cc * 4       \
                                       : g_Xc + (size_t)(m0 + r) * DIN + _k0 + cc * 4;\
                CP16(smem_u32(&_A[r * 36 + cc * 4]), _s);                             \
            } else {                                                                  \
                int c2 = c - 1024, r = c2 >> 3, cc = c2 & 7;                          \
                const float* _s = _ext ? g_BE + (size_t)(n0 + r) * NKR + cc * 4       \
                                       : g_Wc + (size_t)(n0 + r) * DIN + _k0 + cc * 4;\
                CP16(smem_u32(&_B[r * 36 + cc * 4]), _s);                             \
            }                                                                         \
        }                                                                             \
        CP_COMMIT();                                                                  \
    } while (0)

#define G_COMPUTE(i) do {                                                             \
        int _slot2 = (i) % G_NS;                                                      \
        float* A = sm + _slot2 * G_STAGE;                                             \
        float* B = A + G_AF;                                                          \
        _Pragma("unroll")                                                             \
        for (int ka = 0; ka < 4; ka++) {                                              \
            int kk = ka * 8 + (lane & 3);                                             \
            uint32_t a[4][4];                                                         \
            _Pragma("unroll")                                                         \
            for (int mi = 0; mi < 4; mi++) {                                          \
                int row = wm * 64 + mi * 16 + (lane >> 2);                            \
                a[mi][0] = __float_as_uint(A[row * 36 + kk]);                         \
                a[mi][1] = __float_as_uint(A[(row + 8) * 36 + kk]);                   \
                a[mi][2] = __float_as_uint(A[row * 36 + kk + 4]);                     \
                a[mi][3] = __float_as_uint(A[(row + 8) * 36 + kk + 4]);               \
            }                                                                         \
            _Pragma("unroll")                                                         \
            for (int ni = 0; ni < 8; ni++) {                                          \
                int nr = wn * 64 + ni * 8 + (lane >> 2);                              \
                uint32_t b[2];                                                        \
                b[0] = __float_as_uint(B[nr * 36 + kk]);                              \
                b[1] = __float_as_uint(B[nr * 36 + kk + 4]);                          \
                _Pragma("unroll")                                                     \
                for (int mi = 0; mi < 4; mi++) mma_tf32(acc[mi][ni], a[mi], b);       \
            }                                                                         \
        }                                                                             \
    } while (0)

    G_ISSUE(0);
    G_ISSUE(1);

    // main loop: real prefetch remains (i+2 <= 32)
    for (int i = 0; i < 31; i++) {
        CP_WAIT(1);
        __syncthreads();
        G_COMPUTE(i);
        G_ISSUE(i + 2);
    }
    // drained tail: stages 31, 32 resident
    CP_WAIT(0);
    __syncthreads();
    G_COMPUTE(31);
    G_COMPUTE(32);

    // epilogue: bias + store
#pragma unroll
    for (int ni = 0; ni < 8; ni++) {
        int col = n0 + wn * 64 + ni * 8 + (lane & 3) * 2;
        float b0 = bias[col], b1 = bias[col + 1];
#pragma unroll
        for (int mi = 0; mi < 4; mi++) {
            int row = m0 + wm * 64 + mi * 16 + (lane >> 2);
            float2 v0 = make_float2(acc[mi][ni][0] + b0, acc[mi][ni][1] + b1);
            float2 v1 = make_float2(acc[mi][ni][2] + b0, acc[mi][ni][3] + b1);
            *(float2*)&out[(size_t)row * DOUT + col] = v0;
            *(float2*)&out[(size_t)(row + 8) * DOUT + col] = v1;
        }
    }
}

// ---------------- launch ----------------
extern "C" void kernel_launch(void* const* d_in, const int* in_sizes, int n_in,
                              void* d_out, int out_size) {
    const float* x    = (const float*)d_in[0];
    const float* phi  = (const float*)d_in[1];
    const float* la   = (const float*)d_in[2];
    const float* lb   = (const float*)d_in[3];
    const float* W    = (const float*)d_in[4];
    const float* bias = (const float*)d_in[5];
    const int*   inst = (const int*)d_in[6];
    const int*   pad  = (const int*)d_in[7];
    float* out = (float*)d_out;

    static bool attr_done = false;
    if (!attr_done) {
        cudaFuncSetAttribute(router_mma, cudaFuncAttributeMaxDynamicSharedMemorySize, R_SMEM);
        cudaFuncSetAttribute(gemm_mma, cudaFuncAttributeMaxDynamicSharedMemorySize, G_SMEM);
        attr_done = true;
    }

    setup_kernel<<<136, 256>>>(phi, la, lb, W, inst, pad);
    router_mma<<<(BS * SEQ) / 64, 128, R_SMEM>>>(x);
    scan_kernel<<<BS * NKR, 256>>>();
    wr_prep<<<(BS * SEQ) / 128, 128>>>(pad);
    gemm_mma<<<dim3(DOUT / 256, (BS * SEQ) / 128), 256, G_SMEM>>>(bias, out);
}

// round 6
// speedup vs baseline: 1.5696x; 1.5696x over previous
#include <cuda_runtime.h>
#include <cuda_fp16.h>
#include <cstdint>

#define BS 4
#define SEQ 1024
#define DIN 1024
#define DOUT 1024
#define NKR 32

// ---------------- scratch ----------------
__device__ __align__(128) __half g_Xh[BS * SEQ * DIN];  // fp16 X (written by router)
__device__ __align__(128) __half g_Wh[DOUT * DIN];      // fp16 W
__device__ __align__(128) __half g_WRh[BS * SEQ * NKR]; // adapter K-extension (A side)
__device__ __align__(128) __half g_BEh[DOUT * NKR];     // B_flat transposed [n][kr]
__device__ __align__(128) float g_Y[BS * NKR * SEQ];    // y = x@A -> cumsum over s  [b][kr][s]
__device__ __align__(128) float g_mw[BS * SEQ * 8];     // router logits
__device__ __align__(128) float g_PHIA[40 * DIN];       // [phi|A] transposed, k-contiguous
__device__ int g_meta[8];

// ---------------- helpers ----------------
__device__ __forceinline__ uint32_t smem_u32(const void* p) {
    uint32_t a;
    asm("{ .reg .u64 t; cvta.to.shared.u64 t, %1; cvt.u32.u64 %0, t; }" : "=r"(a) : "l"(p));
    return a;
}
#define CP16(dst, src)  asm volatile("cp.async.cg.shared.global [%0], [%1], 16;" :: "r"(dst), "l"(src))
#define CP_COMMIT()     asm volatile("cp.async.commit_group;" ::: "memory")
#define CP_WAIT(n)      asm volatile("cp.async.wait_group %0;" :: "n"(n) : "memory")

__device__ __forceinline__ uint32_t f2tf32(float f) {
    uint32_t u;
    asm("cvt.rna.tf32.f32 %0, %1;" : "=r"(u) : "f"(f));
    return u;
}
__device__ __forceinline__ void mma_tf32(float c[4], const uint32_t a[4], const uint32_t b[2]) {
    asm volatile(
        "mma.sync.aligned.m16n8k8.row.col.f32.tf32.tf32.f32 "
        "{%0,%1,%2,%3}, {%4,%5,%6,%7}, {%8,%9}, {%0,%1,%2,%3};"
        : "+f"(c[0]), "+f"(c[1]), "+f"(c[2]), "+f"(c[3])
        : "r"(a[0]), "r"(a[1]), "r"(a[2]), "r"(a[3]), "r"(b[0]), "r"(b[1]));
}
#define LDSM4(r0, r1, r2, r3, addr) \
    asm volatile("ldmatrix.sync.aligned.m8n8.x4.shared.b16 {%0,%1,%2,%3}, [%4];" \
        : "=r"(r0), "=r"(r1), "=r"(r2), "=r"(r3) : "r"(addr))
#define MMA_F16(c, a, b0v, b1v) \
    asm volatile("mma.sync.aligned.m16n8k16.row.col.f32.f16.f16.f32 " \
        "{%0,%1,%2,%3}, {%4,%5,%6,%7}, {%8,%9}, {%0,%1,%2,%3};" \
        : "+f"((c)[0]), "+f"((c)[1]), "+f"((c)[2]), "+f"((c)[3]) \
        : "r"((a)[0]), "r"((a)[1]), "r"((a)[2]), "r"((a)[3]), "r"(b0v), "r"(b1v))

// ---------------- K0: setup — mask params, PHIA/BE, W->fp16 ----------------
__global__ void __launch_bounds__(256) setup_kernel(const float* __restrict__ phi,
                                                    const float* __restrict__ la,
                                                    const float* __restrict__ lb,
                                                    const float* __restrict__ W,
                                                    const int* __restrict__ inst,
                                                    const int* __restrict__ pad) {
    int bx = blockIdx.x, tid = threadIdx.x;
    if (bx < 4) {
        int b = bx;
        const int* ib = inst + b * SEQ;
        const int* pb = pad + b * SEQ;
        __shared__ int s_sum, s_fi, s_fp;
        if (tid == 0) { s_sum = 0; s_fi = 1 << 30; s_fp = 1 << 30; }
        __syncthreads();
        int lsum = 0, lfi = 1 << 30, lfp = 1 << 30;
        for (int i = tid; i < SEQ; i += 256) {
            int iv = ib[i];
            lsum += iv;
            if (iv && i < lfi) lfi = i;
            if (pb[i] && i < lfp) lfp = i;
        }
        atomicAdd(&s_sum, lsum);
        atomicMin(&s_fi, lfi);
        atomicMin(&s_fp, lfp);
        __syncthreads();
        if (tid == 0) {
            int fi = (s_fi == (1 << 30)) ? 0 : s_fi;
            int fp = (s_fp == (1 << 30)) ? 0 : s_fp;
            g_meta[b] = fi + s_sum;
            g_meta[4 + b] = fp;
        }
    } else if (bx < 8) {
        for (int idx = (bx - 4) * 256 + tid; idx < 40 * DIN + DOUT * NKR; idx += 1024) {
            if (idx < 40 * DIN) {
                int n = idx >> 10, k = idx & 1023;
                float v;
                if (n < 8) v = phi[k * 8 + n];
                else { int kr = n - 8; v = la[(kr >> 2) * (DIN * 4) + k * 4 + (kr & 3)]; }
                g_PHIA[idx] = v;
            } else {
                int i2 = idx - 40 * DIN;
                int n = i2 >> 5, kr = i2 & 31;
                g_BEh[i2] = __float2half(lb[kr * DOUT + n]);
            }
        }
    } else {
        int id = (bx - 8) * 256 + tid;   // 0..32767
#pragma unroll
        for (int j = 0; j < 8; j++) {
            int f4 = j * 32768 + id;
            float4 v = ((const float4*)W)[f4];
            __half2 h0 = __floats2half2_rn(v.x, v.y);
            __half2 h1 = __floats2half2_rn(v.z, v.w);
            ((__half2*)g_Wh)[f4 * 2] = h0;
            ((__half2*)g_Wh)[f4 * 2 + 1] = h1;
        }
    }
}

// ---------------- K2: router GEMM  [mw|y] = X @ [phi|A]; writes g_Xh as byproduct ----------------
#define R_NS 6
#define R_AF (64 * 36)
#define R_BF (40 * 36)
#define R_STAGE (R_AF + R_BF)
#define R_SMEM (R_NS * R_STAGE * 4)

__global__ void __launch_bounds__(128) router_mma(const float* __restrict__ X) {
    extern __shared__ float sm[];
    int tid = threadIdx.x, wid = tid >> 5, lane = tid & 31;
    int m0 = blockIdx.x * 64;
    float acc[5][4];
#pragma unroll
    for (int n = 0; n < 5; n++)
#pragma unroll
        for (int j = 0; j < 4; j++) acc[n][j] = 0.f;

#define R_ISSUE(it) do {                                                              \
        int _slot = (it) % R_NS;                                                      \
        float* _A = sm + _slot * R_STAGE;                                             \
        float* _B = _A + R_AF;                                                        \
        int _k0 = (it) * 32;                                                          \
        for (int c = tid; c < 832; c += 128) {                                        \
            if (c < 512) {                                                            \
                int r = c >> 3, cc = c & 7;                                           \
                CP16(smem_u32(&_A[r * 36 + cc * 4]),                                  \
                     X + (size_t)(m0 + r) * DIN + _k0 + cc * 4);                      \
            } else {                                                                  \
                int c2 = c - 512, r = c2 >> 3, cc = c2 & 7;                           \
                CP16(smem_u32(&_B[r * 36 + cc * 4]),                                  \
                     g_PHIA + (size_t)r * DIN + _k0 + cc * 4);                        \
            }                                                                         \
        }                                                                             \
        CP_COMMIT();                                                                  \
    } while (0)

#define R_COMPUTE(i) do {                                                             \
        int _slot2 = (i) % R_NS;                                                      \
        float* A = sm + _slot2 * R_STAGE;                                             \
        float* B = A + R_AF;                                                          \
        int k0 = (i) * 32;                                                            \
        _Pragma("unroll")                                                             \
        for (int ka = 0; ka < 4; ka++) {                                              \
            int kk = ka * 8 + (lane & 3);                                             \
            int row = wid * 16 + (lane >> 2);                                         \
            uint32_t a[4];                                                            \
            a[0] = f2tf32(A[row * 36 + kk]);                                          \
            a[1] = f2tf32(A[(row + 8) * 36 + kk]);                                    \
            a[2] = f2tf32(A[row * 36 + kk + 4]);                                      \
            a[3] = f2tf32(A[(row + 8) * 36 + kk + 4]);                                \
            _Pragma("unroll")                                                         \
            for (int n = 0; n < 5; n++) {                                             \
                int nr = n * 8 + (lane >> 2);                                         \
                uint32_t b[2];                                                        \
                b[0] = f2tf32(B[nr * 36 + kk]);                                       \
                b[1] = f2tf32(B[nr * 36 + kk + 4]);                                   \
                mma_tf32(acc[n], a, b);                                               \
            }                                                                         \
        }                                                                             \
        _Pragma("unroll")                                                             \
        for (int j = 0; j < 8; j++) {                                                 \
            int idx = tid + j * 128;                                                  \
            int r = idx >> 4, p = idx & 15;                                           \
            float f0 = A[r * 36 + p * 2];                                             \
            float f1 = A[r * 36 + p * 2 + 1];                                         \
            *(__half2*)&g_Xh[(size_t)(m0 + r) * DIN + k0 + p * 2] =                   \
                __floats2half2_rn(f0, f1);                                            \
        }                                                                             \
    } while (0)

#pragma unroll
    for (int it = 0; it < 5; it++) R_ISSUE(it);

    for (int i = 0; i < 27; i++) {
        CP_WAIT(4);
        __syncthreads();
        R_COMPUTE(i);
        R_ISSUE(i + 5);
    }
    CP_WAIT(0);
    __syncthreads();
    for (int i = 27; i < 32; i++) R_COMPUTE(i);

    // scatter D
    int row = m0 + wid * 16 + (lane >> 2);
#pragma unroll
    for (int n = 0; n < 5; n++) {
#pragma unroll
        for (int j = 0; j < 4; j++) {
            int m = row + ((j >> 1) << 3);
            int col = n * 8 + (lane & 3) * 2 + (j & 1);
            int b = m >> 10, s = m & 1023;
            if (col < 8) g_mw[(((size_t)b << 10) + s) * 8 + col] = acc[n][j];
            else g_Y[((size_t)b * NKR + (col - 8)) * SEQ + s] = acc[n][j];
        }
    }
}

// ---------------- K3: inclusive cumsum (float4 + warp scan) ----------------
__global__ void __launch_bounds__(256) scan_kernel() {
    int tid = threadIdx.x, wid = tid >> 5, lane = tid & 31;
    size_t base = (size_t)blockIdx.x * SEQ;
    float4 v = ((float4*)(g_Y + base))[tid];
    v.y += v.x; v.z += v.y; v.w += v.z;
    float t = v.w;
#pragma unroll
    for (int off = 1; off < 32; off <<= 1) {
        float u = __shfl_up_sync(0xffffffffu, t, off);
        if (lane >= off) t += u;
    }
    float warp_excl = t - v.w;
    __shared__ float wsum[8];
    if (lane == 31) wsum[wid] = t;
    __syncthreads();
    if (wid == 0) {
        float w = (lane < 8) ? wsum[lane] : 0.f;
#pragma unroll
        for (int off = 1; off < 8; off <<= 1) {
            float u = __shfl_up_sync(0xffffffffu, w, off);
            if (lane >= off) w += u;
        }
        if (lane < 8) wsum[lane] = w;
    }
    __syncthreads();
    float blk = warp_excl + (wid > 0 ? wsum[wid - 1] : 0.f);
    v.x += blk; v.y += blk; v.z += blk; v.w += blk;
    ((float4*)(g_Y + base))[tid] = v;
}

// ---------------- K4: wr weights — one warp per token ----------------
__global__ void __launch_bounds__(256) wr_prep(const int* __restrict__ pad) {
    int tid = threadIdx.x, lane = tid & 31;
    int token = blockIdx.x * 8 + (tid >> 5);
    int b = token >> 10, s = token & 1023;
    __half* wr = g_WRh + (size_t)token * NKR;
    if (pad[token] == 0) { wr[lane] = __float2half(0.f); return; }

    float v = g_mw[(size_t)token * 8 + (lane & 7)];
    float mx = v;
#pragma unroll
    for (int o = 1; o < 8; o <<= 1) mx = fmaxf(mx, __shfl_xor_sync(0xffffffffu, mx, o));
    float e = expf(v - mx);
    float se = e;
#pragma unroll
    for (int o = 1; o < 8; o <<= 1) se += __shfl_xor_sync(0xffffffffu, se, o);
    float ev = __shfl_sync(0xffffffffu, e, lane >> 2);   // exp(mw[kr>>2])

    int thresh = g_meta[b], pstart = g_meta[4 + b];
    int m = max(thresh, s + 1);
    int cnt = m - pstart;
    if (cnt < 1) cnt = 1;
    const float* yp = g_Y + ((size_t)(b * NKR + lane)) * SEQ;
    float w = yp[m - 1] - (pstart > 0 ? yp[pstart - 1] : 0.f);
    wr[lane] = __float2half(ev / se * w / (float)cnt);
}

// ---------------- K5: fused fp16 GEMM  out = [Xh|WRh] @ [[Wh^T];[BEh]] + bias ----------------
// BM=128, BN=256, BK=32, K=1056 (33 tiles). 8 warps of 64x64. m16n8k16 + ldmatrix.
#define GH_NS 3
#define GH_A 10240           // 128 rows x 80B
#define GH_ST 30720          // + 256 rows x 80B
#define GH_SMEM (GH_NS * GH_ST)

__global__ void __launch_bounds__(256) gemm_h(const float* __restrict__ bias,
                                              float* __restrict__ out) {
    extern __shared__ char smc[];
    uint32_t sb = smem_u32(smc);
    int tid = threadIdx.x, wid = tid >> 5, lane = tid & 31;
    int wm = wid >> 2, wn = wid & 3;
    int m0 = blockIdx.y * 128, n0 = blockIdx.x * 256;

    float acc[4][8][4];
#pragma unroll
    for (int i = 0; i < 4; i++)
#pragma unroll
        for (int j = 0; j < 8; j++)
#pragma unroll
            for (int k = 0; k < 4; k++) acc[i][j][k] = 0.f;

    // per-lane ldmatrix offsets
    int aRow = (lane & 7) | (((lane >> 3) & 1) << 3);   // 0..15
    int aKb  = (lane >> 4) * 16;                        // byte offset within k16
    int bRow = (lane & 7) | (((lane >> 4) & 1) << 3);
    int bKb  = ((lane >> 3) & 1) * 16;

#define GH_ISSUE(it) do {                                                             \
        int _slot = (it) % GH_NS;                                                     \
        uint32_t _Au = sb + _slot * GH_ST;                                            \
        uint32_t _Bu = _Au + GH_A;                                                    \
        int _k0 = (it) * 32;                                                          \
        bool _ext = ((it) == 32);                                                     \
        for (int c = tid; c < 1536; c += 256) {                                       \
            if (c < 512) {                                                            \
                int r = c >> 2, ch = c & 3;                                           \
                const __half* _s = _ext                                               \
                    ? g_WRh + (size_t)(m0 + r) * NKR + ch * 8                         \
                    : g_Xh + (size_t)(m0 + r) * DIN + _k0 + ch * 8;                   \
                CP16(_Au + r * 80 + ch * 16, _s);                                     \
            } else {                                                                  \
                int c2 = c - 512, r = c2 >> 2, ch = c2 & 3;                           \
                const __half* _s = _ext                                               \
                    ? g_BEh + (size_t)(n0 + r) * NKR + ch * 8                         \
                    : g_Wh + (size_t)(n0 + r) * DIN + _k0 + ch * 8;                   \
                CP16(_Bu + r * 80 + ch * 16, _s);                                     \
            }                                                                         \
        }                                                                             \
        CP_COMMIT();                                                                  \
    } while (0)

#define GH_COMPUTE(i) do {                                                            \
        int _slot2 = (i) % GH_NS;                                                     \
        uint32_t Au = sb + _slot2 * GH_ST;                                            \
        uint32_t Bu = Au + GH_A;                                                      \
        _Pragma("unroll")                                                             \
        for (int ka = 0; ka < 2; ka++) {                                              \
            int kb = ka * 32;                                                         \
            uint32_t a[4][4];                                                         \
            _Pragma("unroll")                                                         \
            for (int mi = 0; mi < 4; mi++) {                                          \
                uint32_t ad = Au + (wm * 64 + mi * 16 + aRow) * 80 + kb + aKb;        \
                LDSM4(a[mi][0], a[mi][1], a[mi][2], a[mi][3], ad);                    \
            }                                                                         \
            _Pragma("unroll")                                                         \
            for (int ni2 = 0; ni2 < 4; ni2++) {                                       \
                uint32_t bd = Bu + (wn * 64 + ni2 * 16 + bRow) * 80 + kb + bKb;       \
                uint32_t r0, r1, r2, r3;                                              \
                LDSM4(r0, r1, r2, r3, bd);                                            \
                _Pragma("unroll")                                                     \
                for (int mi = 0; mi < 4; mi++) {                                      \
                    MMA_F16(acc[mi][ni2 * 2], a[mi], r0, r1);                         \
                    MMA_F16(acc[mi][ni2 * 2 + 1], a[mi], r2, r3);                     \
                }                                                                     \
            }                                                                         \
        }                                                                             \
    } while (0)

    GH_ISSUE(0);
    GH_ISSUE(1);

    for (int i = 0; i < 31; i++) {
        CP_WAIT(1);
        __syncthreads();
        GH_COMPUTE(i);
        GH_ISSUE(i + 2);
    }
    CP_WAIT(0);
    __syncthreads();
    GH_COMPUTE(31);
    GH_COMPUTE(32);

    // epilogue: bias + store
#pragma unroll
    for (int ni = 0; ni < 8; ni++) {
        int col = n0 + wn * 64 + ni * 8 + (lane & 3) * 2;
        float b0 = bias[col], b1 = bias[col + 1];
#pragma unroll
        for (int mi = 0; mi < 4; mi++) {
            int row = m0 + wm * 64 + mi * 16 + (lane >> 2);
            float2 v0 = make_float2(acc[mi][ni][0] + b0, acc[mi][ni][1] + b1);
            float2 v1 = make_float2(acc[mi][ni][2] + b0, acc[mi][ni][3] + b1);
            *(float2*)&out[(size_t)row * DOUT + col] = v0;
            *(float2*)&out[(size_t)(row + 8) * DOUT + col] = v1;
        }
    }
}

// ---------------- launch ----------------
extern "C" void kernel_launch(void* const* d_in, const int* in_sizes, int n_in,
                              void* d_out, int out_size) {
    const float* x    = (const float*)d_in[0];
    const float* phi  = (const float*)d_in[1];
    const float* la   = (const float*)d_in[2];
    const float* lb   = (const float*)d_in[3];
    const float* W    = (const float*)d_in[4];
    const float* bias = (const float*)d_in[5];
    const int*   inst = (const int*)d_in[6];
    const int*   pad  = (const int*)d_in[7];
    float* out = (float*)d_out;

    static bool attr_done = false;
    if (!attr_done) {
        cudaFuncSetAttribute(router_mma, cudaFuncAttributeMaxDynamicSharedMemorySize, R_SMEM);
        cudaFuncSetAttribute(gemm_h, cudaFuncAttributeMaxDynamicSharedMemorySize, GH_SMEM);
        attr_done = true;
    }

    setup_kernel<<<136, 256>>>(phi, la, lb, W, inst, pad);
    router_mma<<<(BS * SEQ) / 64, 128, R_SMEM>>>(x);
    scan_kernel<<<BS * NKR, 256>>>();
    wr_prep<<<(BS * SEQ) / 8, 256>>>(pad);
    gemm_h<<<dim3(DOUT / 256, (BS * SEQ) / 128), 256, GH_SMEM>>>(bias, out);
}

// round 9
// speedup vs baseline: 1.8862x; 1.2017x over previous
#include <cuda_runtime.h>
#include <cuda_fp16.h>
#include <cstdint>

#define BS 4
#define SEQ 1024
#define DIN 1024
#define DOUT 1024
#define NKR 32

// ---------------- scratch ----------------
__device__ __align__(128) __half g_Xh[BS * SEQ * DIN];  // fp16 X (written by setup)
__device__ __align__(128) __half g_Wh[DOUT * DIN];      // fp16 W
__device__ __align__(128) __half g_WRh[BS * SEQ * NKR]; // adapter K-extension (A side)
__device__ __align__(128) __half g_BEh[DOUT * NKR];     // B_flat transposed [n][kr]
__device__ __align__(128) __half g_PHIAh[48 * DIN];     // [phi|A] fp16, k-contig, 48 rows (40-47 zero)
__device__ __align__(128) float g_Y[BS * NKR * SEQ];    // y = x@A -> cumsum over s  [b][kr][s]
__device__ __align__(128) float g_mw[BS * SEQ * 8];     // router logits
__device__ int g_meta[8];

// ---------------- helpers ----------------
__device__ __forceinline__ uint32_t smem_u32(const void* p) {
    uint32_t a;
    asm("{ .reg .u64 t; cvta.to.shared.u64 t, %1; cvt.u32.u64 %0, t; }" : "=r"(a) : "l"(p));
    return a;
}
#define CP16(dst, src)  asm volatile("cp.async.cg.shared.global [%0], [%1], 16;" :: "r"(dst), "l"(src))
#define CP_COMMIT()     asm volatile("cp.async.commit_group;" ::: "memory")
#define CP_WAIT(n)      asm volatile("cp.async.wait_group %0;" :: "n"(n) : "memory")
#define LDSM4(r0, r1, r2, r3, addr) \
    asm volatile("ldmatrix.sync.aligned.m8n8.x4.shared.b16 {%0,%1,%2,%3}, [%4];" \
        : "=r"(r0), "=r"(r1), "=r"(r2), "=r"(r3) : "r"(addr))
#define MMA_F16(c, a, b0v, b1v) \
    asm volatile("mma.sync.aligned.m16n8k16.row.col.f32.f16.f16.f32 " \
        "{%0,%1,%2,%3}, {%4,%5,%6,%7}, {%8,%9}, {%0,%1,%2,%3};" \
        : "+f"((c)[0]), "+f"((c)[1]), "+f"((c)[2]), "+f"((c)[3]) \
        : "r"((a)[0]), "r"((a)[1]), "r"((a)[2]), "r"((a)[3]), "r"(b0v), "r"(b1v))

// ---------------- K0: setup — mask, PHIAh/BEh, W->fp16, X->fp16 ----------------
__global__ void __launch_bounds__(256) setup_kernel(const float* __restrict__ X,
                                                    const float* __restrict__ phi,
                                                    const float* __restrict__ la,
                                                    const float* __restrict__ lb,
                                                    const float* __restrict__ W,
                                                    const int* __restrict__ inst,
                                                    const int* __restrict__ pad) {
    int bx = blockIdx.x, tid = threadIdx.x;
    if (bx < 4) {
        int b = bx;
        const int* ib = inst + b * SEQ;
        const int* pb = pad + b * SEQ;
        __shared__ int s_sum, s_fi, s_fp;
        if (tid == 0) { s_sum = 0; s_fi = 1 << 30; s_fp = 1 << 30; }
        __syncthreads();
        int lsum = 0, lfi = 1 << 30, lfp = 1 << 30;
        for (int i = tid; i < SEQ; i += 256) {
            int iv = ib[i];
            lsum += iv;
            if (iv && i < lfi) lfi = i;
            if (pb[i] && i < lfp) lfp = i;
        }
        atomicAdd(&s_sum, lsum);
        atomicMin(&s_fi, lfi);
        atomicMin(&s_fp, lfp);
        __syncthreads();
        if (tid == 0) {
            int fi = (s_fi == (1 << 30)) ? 0 : s_fi;
            int fp = (s_fp == (1 << 30)) ? 0 : s_fp;
            g_meta[b] = fi + s_sum;
            g_meta[4 + b] = fp;
        }
    } else if (bx < 8) {
        // PHIAh [48][1024] (rows 40-47 zero) + BEh [1024][32]
        for (int idx = (bx - 4) * 256 + tid; idx < 48 * DIN + DOUT * NKR; idx += 1024) {
            if (idx < 48 * DIN) {
                int n = idx >> 10, k = idx & 1023;
                float v = 0.f;
                if (n < 8) v = phi[k * 8 + n];
                else if (n < 40) { int kr = n - 8; v = la[(kr >> 2) * (DIN * 4) + k * 4 + (kr & 3)]; }
                g_PHIAh[idx] = __float2half(v);
            } else {
                int i2 = idx - 48 * DIN;
                int n = i2 >> 5, kr = i2 & 31;
                g_BEh[i2] = __float2half(lb[kr * DOUT + n]);
            }
        }
    } else if (bx < 136) {
        // W -> g_Wh
        int id = (bx - 8) * 256 + tid;   // 0..32767
#pragma unroll
        for (int j = 0; j < 8; j++) {
            int f4 = j * 32768 + id;
            float4 v = ((const float4*)W)[f4];
            ((__half2*)g_Wh)[f4 * 2] = __floats2half2_rn(v.x, v.y);
            ((__half2*)g_Wh)[f4 * 2 + 1] = __floats2half2_rn(v.z, v.w);
        }
    } else {
        // X -> g_Xh (512 blocks)
        int id = (bx - 136) * 256 + tid; // 0..131071
#pragma unroll
        for (int j = 0; j < 8; j++) {
            int f4 = j * 131072 + id;
            float4 v = ((const float4*)X)[f4];
            ((__half2*)g_Xh)[f4 * 2] = __floats2half2_rn(v.x, v.y);
            ((__half2*)g_Xh)[f4 * 2 + 1] = __floats2half2_rn(v.z, v.w);
        }
    }
}

// ---------------- K2: router fp16 GEMM  [mw|y] = Xh @ PHIAh^T ----------------
// BM=64, N=48 (cols 40-47 discarded), BK=64, 128 threads (4 warps x m16), 4-stage cp.async.
#define R_NS 4
#define R_LD 144                 // 64 halves = 128B + 16B pad
#define R_A (64 * R_LD)
#define R_B (48 * R_LD)
#define R_ST (R_A + R_B)
#define R_SMEM (R_NS * R_ST)

__global__ void __launch_bounds__(128) router_mma(int dummy) {
    extern __shared__ char smr[];
    uint32_t sb = smem_u32(smr);
    int tid = threadIdx.x, wid = tid >> 5, lane = tid & 31;
    int m0 = blockIdx.x * 64;

    float acc[6][4];
#pragma unroll
    for (int n = 0; n < 6; n++)
#pragma unroll
        for (int j = 0; j < 4; j++) acc[n][j] = 0.f;

    int aRow = (lane & 7) | (((lane >> 3) & 1) << 3);
    int aKb  = (lane >> 4) * 16;
    int bRow = (lane & 7) | (((lane >> 4) & 1) << 3);
    int bKb  = ((lane >> 3) & 1) * 16;

#define R_ISSUE(it) do {                                                              \
        int _slot = (it) % R_NS;                                                      \
        uint32_t _Au = sb + _slot * R_ST;                                             \
        uint32_t _Bu = _Au + R_A;                                                     \
        int _k0 = (it) * 64;                                                          \
        for (int c = tid; c < 896; c += 128) {                                        \
            if (c < 512) {                                                            \
                int r = c >> 3, ch = c & 7;                                           \
                CP16(_Au + r * R_LD + ch * 16,                                        \
                     g_Xh + (size_t)(m0 + r) * DIN + _k0 + ch * 8);                   \
            } else {                                                                  \
                int c2 = c - 512, r = c2 >> 3, ch = c2 & 7;                           \
                CP16(_Bu + r * R_LD + ch * 16,                                        \
                     g_PHIAh + (size_t)r * DIN + _k0 + ch * 8);                       \
            }                                                                         \
        }                                                                             \
        CP_COMMIT();                                                                  \
    } while (0)

#define R_COMPUTE(i) do {                                                             \
        uint32_t Au = sb + ((i) % R_NS) * R_ST;                                       \
        uint32_t Bu = Au + R_A;                                                       \
        _Pragma("unroll")                                                             \
        for (int ka = 0; ka < 4; ka++) {                                              \
            uint32_t a[4];                                                            \
            LDSM4(a[0], a[1], a[2], a[3],                                             \
                  Au + (wid * 16 + aRow) * R_LD + ka * 32 + aKb);                     \
            _Pragma("unroll")                                                         \
            for (int p = 0; p < 3; p++) {                                             \
                uint32_t r0, r1, r2, r3;                                              \
                LDSM4(r0, r1, r2, r3,                                                 \
                      Bu + (p * 16 + bRow) * R_LD + ka * 32 + bKb);                   \
                MMA_F16(acc[p * 2], a, r0, r1);                                       \
                MMA_F16(acc[p * 2 + 1], a, r2, r3);                                   \
            }                                                                         \
        }                                                                             \
    } while (0)

    R_ISSUE(0); R_ISSUE(1); R_ISSUE(2);
    for (int i = 0; i < 13; i++) {
        CP_WAIT(2);
        __syncthreads();
        R_COMPUTE(i);
        R_ISSUE(i + 3);
    }
    CP_WAIT(0);
    __syncthreads();
    R_COMPUTE(13);
    R_COMPUTE(14);
    R_COMPUTE(15);

    // scatter D: cols 0-7 -> mw, 8-39 -> Y, 40-47 discarded
    int rowb = m0 + wid * 16 + (lane >> 2);
#pragma unroll
    for (int n = 0; n < 6; n++) {
#pragma unroll
        for (int j = 0; j < 4; j++) {
            int m = rowb + ((j >> 1) << 3);
            int col = n * 8 + (lane & 3) * 2 + (j & 1);
            int b = m >> 10, s = m & 1023;
            if (col < 8) g_mw[(((size_t)b << 10) + s) * 8 + col] = acc[n][j];
            else if (col < 40) g_Y[((size_t)b * NKR + (col - 8)) * SEQ + s] = acc[n][j];
        }
    }
}

// ---------------- K3: inclusive cumsum (float4 + warp scan) ----------------
__global__ void __launch_bounds__(256) scan_kernel() {
    int tid = threadIdx.x, wid = tid >> 5, lane = tid & 31;
    size_t base = (size_t)blockIdx.x * SEQ;
    float4 v = ((float4*)(g_Y + base))[tid];
    v.y += v.x; v.z += v.y; v.w += v.z;
    float t = v.w;
#pragma unroll
    for (int off = 1; off < 32; off <<= 1) {
        float u = __shfl_up_sync(0xffffffffu, t, off);
        if (lane >= off) t += u;
    }
    float warp_excl = t - v.w;
    __shared__ float wsum[8];
    if (lane == 31) wsum[wid] = t;
    __syncthreads();
    if (wid == 0) {
        float w = (lane < 8) ? wsum[lane] : 0.f;
#pragma unroll
        for (int off = 1; off < 8; off <<= 1) {
            float u = __shfl_up_sync(0xffffffffu, w, off);
            if (lane >= off) w += u;
        }
        if (lane < 8) wsum[lane] = w;
    }
    __syncthreads();
    float blk = warp_excl + (wid > 0 ? wsum[wid - 1] : 0.f);
    v.x += blk; v.y += blk; v.z += blk; v.w += blk;
    ((float4*)(g_Y + base))[tid] = v;
}

// ---------------- K4: wr weights — one warp per token ----------------
__global__ void __launch_bounds__(256) wr_prep(const int* __restrict__ pad) {
    int tid = threadIdx.x, lane = tid & 31;
    int token = blockIdx.x * 8 + (tid >> 5);
    int b = token >> 10, s = token & 1023;
    __half* wr = g_WRh + (size_t)token * NKR;
    if (pad[token] == 0) { wr[lane] = __float2half(0.f); return; }

    float v = g_mw[(size_t)token * 8 + (lane & 7)];
    float mx = v;
#pragma unroll
    for (int o = 1; o < 8; o <<= 1) mx = fmaxf(mx, __shfl_xor_sync(0xffffffffu, mx, o));
    float e = expf(v - mx);
    float se = e;
#pragma unroll
    for (int o = 1; o < 8; o <<= 1) se += __shfl_xor_sync(0xffffffffu, se, o);
    float ev = __shfl_sync(0xffffffffu, e, lane >> 2);

    int thresh = g_meta[b], pstart = g_meta[4 + b];
    int m = max(thresh, s + 1);
    int cnt = m - pstart;
    if (cnt < 1) cnt = 1;
    const float* yp = g_Y + ((size_t)(b * NKR + lane)) * SEQ;
    float w = yp[m - 1] - (pstart > 0 ? yp[pstart - 1] : 0.f);
    wr[lane] = __float2half(ev / se * w / (float)cnt);
}

// ---------------- K5: fused fp16 GEMM  out = [Xh|WRh] @ [[Wh^T];[BEh]] + bias ----------------
// BM=128, BN=256, BK=32, K=1056 (33 tiles). 8 warps of 64x64. 4-stage cp.async.
#define GH_NS 4
#define GH_A 10240           // 128 rows x 80B
#define GH_ST 30720          // + 256 rows x 80B
#define GH_SMEM (GH_NS * GH_ST)

__global__ void __launch_bounds__(256) gemm_h(const float* __restrict__ bias,
                                              float* __restrict__ out) {
    extern __shared__ char smc[];
    uint32_t sb = smem_u32(smc);
    int tid = threadIdx.x, wid = tid >> 5, lane = tid & 31;
    int wm = wid >> 2, wn = wid & 3;
    int m0 = blockIdx.y * 128, n0 = blockIdx.x * 256;

    float acc[4][8][4];
#pragma unroll
    for (int i = 0; i < 4; i++)
#pragma unroll
        for (int j = 0; j < 8; j++)
#pragma unroll
            for (int k = 0; k < 4; k++) acc[i][j][k] = 0.f;

    int aRow = (lane & 7) | (((lane >> 3) & 1) << 3);
    int aKb  = (lane >> 4) * 16;
    int bRow = (lane & 7) | (((lane >> 4) & 1) << 3);
    int bKb  = ((lane >> 3) & 1) * 16;

#define GH_ISSUE(it) do {                                                             \
        int _slot = (it) % GH_NS;                                                     \
        uint32_t _Au = sb + _slot * GH_ST;                                            \
        uint32_t _Bu = _Au + GH_A;                                                    \
        int _k0 = (it) * 32;                                                          \
        bool _ext = ((it) == 32);                                                     \
        for (int c = tid; c < 1536; c += 256) {                                       \
            if (c < 512) {                                                            \
                int r = c >> 2, ch = c & 3;                                           \
                const __half* _s = _ext                                               \
                    ? g_WRh + (size_t)(m0 + r) * NKR + ch * 8                         \
                    : g_Xh + (size_t)(m0 + r) * DIN + _k0 + ch * 8;                   \
                CP16(_Au + r * 80 + ch * 16, _s);                                     \
            } else {                                                                  \
                int c2 = c - 512, r = c2 >> 2, ch = c2 & 3;                           \
                const __half* _s = _ext                                               \
                    ? g_BEh + (size_t)(n0 + r) * NKR + ch * 8                         \
                    : g_Wh + (size_t)(n0 + r) * DIN + _k0 + ch * 8;                   \
                CP16(_Bu + r * 80 + ch * 16, _s);                                     \
            }                                                                         \
        }                                                                             \
        CP_COMMIT();                                                                  \
    } while (0)

#define GH_COMPUTE(i) do {                                                            \
        uint32_t Au = sb + ((i) % GH_NS) * GH_ST;                                     \
        uint32_t Bu = Au + GH_A;                                                      \
        _Pragma("unroll")                                                             \
        for (int ka = 0; ka < 2; ka++) {                                              \
            int kb = ka * 32;                                                         \
            uint32_t a[4][4];                                                         \
            _Pragma("unroll")                                                         \
            for (int mi = 0; mi < 4; mi++) {                                          \
                uint32_t ad = Au + (wm * 64 + mi * 16 + aRow) * 80 + kb + aKb;        \
                LDSM4(a[mi][0], a[mi][1], a[mi][2], a[mi][3], ad);                    \
            }                                                                         \
            _Pragma("unroll")                                                         \
            for (int ni2 = 0; ni2 < 4; ni2++) {                                       \
                uint32_t bd = Bu + (wn * 64 + ni2 * 16 + bRow) * 80 + kb + bKb;       \
                uint32_t r0, r1, r2, r3;                                              \
                LDSM4(r0, r1, r2, r3, bd);                                            \
                _Pragma("unroll")                                                     \
                for (int mi = 0; mi < 4; mi++) {                                      \
                    MMA_F16(acc[mi][ni2 * 2], a[mi], r0, r1);                         \
                    MMA_F16(acc[mi][ni2 * 2 + 1], a[mi], r2, r3);                     \
                }                                                                     \
            }                                                                         \
        }                                                                             \
    } while (0)

    GH_ISSUE(0); GH_ISSUE(1); GH_ISSUE(2);

    for (int i = 0; i < 30; i++) {
        CP_WAIT(2);
        __syncthreads();
        GH_COMPUTE(i);
        GH_ISSUE(i + 3);
    }
    CP_WAIT(0);
    __syncthreads();
    GH_COMPUTE(30);
    GH_COMPUTE(31);
    GH_COMPUTE(32);

    // epilogue: bias + store
#pragma unroll
    for (int ni = 0; ni < 8; ni++) {
        int col = n0 + wn * 64 + ni * 8 + (lane & 3) * 2;
        float b0 = bias[col], b1 = bias[col + 1];
#pragma unroll
        for (int mi = 0; mi < 4; mi++) {
            int row = m0 + wm * 64 + mi * 16 + (lane >> 2);
            float2 v0 = make_float2(acc[mi][ni][0] + b0, acc[mi][ni][1] + b1);
            float2 v1 = make_float2(acc[mi][ni][2] + b0, acc[mi][ni][3] + b1);
            *(float2*)&out[(size_t)row * DOUT + col] = v0;
            *(float2*)&out[(size_t)(row + 8) * DOUT + col] = v1;
        }
    }
}

// ---------------- launch ----------------
extern "C" void kernel_launch(void* const* d_in, const int* in_sizes, int n_in,
                              void* d_out, int out_size) {
    const float* x    = (const float*)d_in[0];
    const float* phi  = (const float*)d_in[1];
    const float* la   = (const float*)d_in[2];
    const float* lb   = (const float*)d_in[3];
    const float* W    = (const float*)d_in[4];
    const float* bias = (const float*)d_in[5];
    const int*   inst = (const int*)d_in[6];
    const int*   pad  = (const int*)d_in[7];
    float* out = (float*)d_out;

    static bool attr_done = false;
    if (!attr_done) {
        cudaFuncSetAttribute(router_mma, cudaFuncAttributeMaxDynamicSharedMemorySize, R_SMEM);
        cudaFuncSetAttribute(gemm_h, cudaFuncAttributeMaxDynamicSharedMemorySize, GH_SMEM);
        attr_done = true;
    }

    setup_kernel<<<648, 256>>>(x, phi, la, lb, W, inst, pad);
    router_mma<<<(BS * SEQ) / 64, 128, R_SMEM>>>(0);
    scan_kernel<<<BS * NKR, 256>>>();
    wr_prep<<<(BS * SEQ) / 8, 256>>>(pad);
    gemm_h<<<dim3(DOUT / 256, (BS * SEQ) / 128), 256, GH_SMEM>>>(bias, out);
}